// round 11
// baseline (speedup 1.0000x reference)
#include <cuda_runtime.h>
#include <cuda_fp16.h>
#include <math.h>
#include <stdint.h>

// ---------------- problem constants ----------------
#define B_SZ  2
#define L_SZ  2048
#define DM    1024
#define DIN   2048
#define NST   16
#define DTR   64
#define M_ROWS (B_SZ * L_SZ)   // 4096
#define XPROJ_N (DTR + 2*NST)  // 96

// ---------------- scratch ----------------
__device__ __align__(256) float g_xz[M_ROWS * 2 * DIN];
__device__ __align__(256) float g_uc[M_ROWS * DIN];
__device__ __align__(256) float g_dbc[M_ROWS * XPROJ_N];
__device__ __align__(256) float g_delta[M_ROWS * DIN];

// split-fp16 operands. A-side: [M][2K] = [hi|lo]. B-side: [N][K] = hi only.
__device__ __align__(256) __half gA1 [M_ROWS * 2 * DM];
__device__ __align__(256) __half gB1 [(2*DIN) * DM];
__device__ __align__(256) __half gAdt[M_ROWS * 2 * DTR];
__device__ __align__(256) __half gBdt[DIN * DTR];
__device__ __align__(256) __half gAy [M_ROWS * 2 * DIN];   // written by scan (hi|lo)
__device__ __align__(256) __half gBo [DM * DIN];

// ---------------- PTX helpers ----------------
__device__ __forceinline__ uint32_t smem_u32(const void* p) {
    uint32_t a;
    asm("{ .reg .u64 t; cvta.to.shared.u64 t, %1; cvt.u32.u64 %0, t; }" : "=r"(a) : "l"(p));
    return a;
}
#define CP_ASYNC16(dst, src) \
    asm volatile("cp.async.cg.shared.global [%0], [%1], 16;" :: "r"(dst), "l"(src) : "memory")
#define CP_COMMIT() asm volatile("cp.async.commit_group;" ::: "memory")
#define CP_WAIT(n)  asm volatile("cp.async.wait_group %0;" :: "n"(n) : "memory")
#define LDSM_X4(r, a) \
    asm volatile("ldmatrix.sync.aligned.m8n8.x4.shared.b16 {%0,%1,%2,%3}, [%4];" \
        : "=r"((r)[0]), "=r"((r)[1]), "=r"((r)[2]), "=r"((r)[3]) : "r"(a))
#define MMA16816(c, a, b0, b1) \
    asm volatile("mma.sync.aligned.m16n8k16.row.col.f32.f16.f16.f32 " \
        "{%0,%1,%2,%3}, {%4,%5,%6,%7}, {%8,%9}, {%0,%1,%2,%3};" \
        : "+f"((c)[0]), "+f"((c)[1]), "+f"((c)[2]), "+f"((c)[3]) \
        : "r"((a)[0]), "r"((a)[1]), "r"((a)[2]), "r"((a)[3]), "r"(b0), "r"(b1))

// ---------------- ln + expand:  x -> [hi|lo] fp16 ----------------
__global__ __launch_bounds__(256) void ln_expand(const float* __restrict__ x,
                                                 const float* __restrict__ g,
                                                 const float* __restrict__ bb) {
    int row = blockIdx.x;
    int t = threadIdx.x;
    float4 v = ((const float4*)(x + (size_t)row * DM))[t];
    float s  = v.x + v.y + v.z + v.w;
    float sq = v.x*v.x + v.y*v.y + v.z*v.z + v.w*v.w;
    #pragma unroll
    for (int o = 16; o > 0; o >>= 1) {
        s  += __shfl_xor_sync(0xffffffffu, s, o);
        sq += __shfl_xor_sync(0xffffffffu, sq, o);
    }
    __shared__ float rs[8], rq[8];
    int wid = t >> 5, lane = t & 31;
    if (lane == 0) { rs[wid] = s; rq[wid] = sq; }
    __syncthreads();
    float S = 0.f, Q = 0.f;
    #pragma unroll
    for (int i = 0; i < 8; i++) { S += rs[i]; Q += rq[i]; }
    float mean = S * (1.0f / DM);
    float var  = Q * (1.0f / DM) - mean * mean;
    float rstd = rsqrtf(var + 1e-5f);
    float4 gg = ((const float4*)g)[t];
    float4 bv = ((const float4*)bb)[t];
    float o[4];
    o[0] = (v.x - mean) * rstd * gg.x + bv.x;
    o[1] = (v.y - mean) * rstd * gg.y + bv.y;
    o[2] = (v.z - mean) * rstd * gg.z + bv.z;
    o[3] = (v.w - mean) * rstd * gg.w + bv.w;
    __half hi[4], lo[4];
    #pragma unroll
    for (int i = 0; i < 4; i++) {
        hi[i] = __float2half_rn(o[i]);
        lo[i] = __float2half_rn(o[i] - __half2float(hi[i]));
    }
    size_t base = (size_t)row * (2 * DM);
    int k = t * 4;
    *(uint64_t*)(gA1 + base + k)      = *(uint64_t*)hi;
    *(uint64_t*)(gA1 + base + DM + k) = *(uint64_t*)lo;
}

// ---------------- generic A expand: A[M,K] (stride ldin) -> [hi|lo] ----------------
__global__ __launch_bounds__(256) void aexp(const float* __restrict__ A, int ldin,
                                            __half* __restrict__ Ap, int K, int M) {
    int kq = K >> 2;
    int idx = blockIdx.x * blockDim.x + threadIdx.x;
    if (idx >= M * kq) return;
    int m = idx / kq, k = (idx - m * kq) * 4;
    float4 v = *(const float4*)(A + (size_t)m * ldin + k);
    float o[4] = {v.x, v.y, v.z, v.w};
    __half hi[4], lo[4];
    #pragma unroll
    for (int i = 0; i < 4; i++) {
        hi[i] = __float2half_rn(o[i]);
        lo[i] = __float2half_rn(o[i] - __half2float(hi[i]));
    }
    size_t base = (size_t)m * (2 * K);
    *(uint64_t*)(Ap + base + k)     = *(uint64_t*)hi;
    *(uint64_t*)(Ap + base + K + k) = *(uint64_t*)lo;
}

// ---------------- weight transpose: W[K,N] -> Bp[N,K] = hi fp16 ----------------
__global__ __launch_bounds__(256) void wexpT(const float* __restrict__ W,
                                             __half* __restrict__ Bp, int K, int N) {
    __shared__ float tile[32][33];
    int k0 = blockIdx.y * 32, n0 = blockIdx.x * 32;
    int tx = threadIdx.x & 31, ty = threadIdx.x >> 5;
    #pragma unroll
    for (int i = 0; i < 32; i += 8)
        tile[ty + i][tx] = W[(size_t)(k0 + ty + i) * N + n0 + tx];
    __syncthreads();
    #pragma unroll
    for (int i = 0; i < 32; i += 8) {
        int n = n0 + ty + i;
        int k = k0 + tx;
        Bp[(size_t)n * K + k] = __float2half_rn(tile[tx][ty + i]);
    }
}

// ---------------- shared-B split GEMM: C = (Ah+Al)[M,K] @ Bh[N,K]^T ----------------
// Block 128x128, BK=32 (native K), 8 warps (4m x 2n), warp tile 32x64.
// A tile: 128 rows x 128B ([hi 64B | lo 64B]), swizzle (c ^ (r&7))*16.
// B tile: 128 rows x  64B,                  swizzle (c ^ ((r>>1)&3))*16.
// Each B fragment used by 2 mma (A-hi, A-lo). 48KB static smem, 2 CTAs/SM.
template <int EPI>
__global__ __launch_bounds__(256, 2) void gemm_mma(
    const __half* __restrict__ Ag,
    const __half* __restrict__ Bg,
    int K, float* __restrict__ C, int ldc,
    const float* __restrict__ extra, int lde)
{
    __shared__ __align__(1024) char smA[2][16384];
    __shared__ __align__(1024) char smB[2][8192];

    int tid = threadIdx.x, lane = tid & 31, wid = tid >> 5;
    int m0 = blockIdx.y * 128, n0 = blockIdx.x * 128;
    int wm = (wid & 3) * 32, wn = (wid >> 2) * 64;

    float c[2][8][4];
    #pragma unroll
    for (int t = 0; t < 2; t++)
        #pragma unroll
        for (int j = 0; j < 8; j++)
            #pragma unroll
            for (int q = 0; q < 4; q++) c[t][j][q] = 0.f;

    const __half* Arow = Ag + (size_t)m0 * (2 * K);
    const __half* Brow = Bg + (size_t)n0 * K;

    // A copy: thread t -> row ar = t>>1, half ah = t&1 (0=hi,1=lo), 4 chunks (64B)
    int ar = tid >> 1, ah = tid & 1;
    // B copy: thread t -> row br = t>>1, 2 chunks starting bc0 (32B)
    int br = tid >> 1, bc0 = (tid & 1) * 2;

    uint32_t sA[2] = { smem_u32(&smA[0][0]), smem_u32(&smA[1][0]) };
    uint32_t sB[2] = { smem_u32(&smB[0][0]), smem_u32(&smB[1][0]) };

    auto issue = [&](int buf, int kt) {
        const __half* ga = Arow + (size_t)ar * (2 * K) + ah * K + kt;
        #pragma unroll
        for (int cc = 0; cc < 4; cc++) {
            int chunk = ah * 4 + cc;
            CP_ASYNC16(sA[buf] + ar * 128 + (((chunk ^ (ar & 7)) << 4)), ga + cc * 8);
        }
        const __half* gb = Brow + (size_t)br * K + kt;
        #pragma unroll
        for (int cc = 0; cc < 2; cc++) {
            int chunk = bc0 + cc;
            CP_ASYNC16(sB[buf] + br * 64 + (((chunk ^ ((br >> 1) & 3)) << 4)), gb + chunk * 8);
        }
        CP_COMMIT();
    };

    // ldmatrix lane geometry
    int arow = lane & 15;
    int aoff = (lane & 16) ? 1 : 0;
    int brow = (lane & 7) + ((lane & 16) ? 8 : 0);
    int boff = (lane & 8) ? 1 : 0;

    int nIter = K / 32;
    issue(0, 0);

    for (int it = 0; it < nIter; it++) {
        int cur = it & 1;
        if (it + 1 < nIter) { issue(cur ^ 1, (it + 1) * 32); CP_WAIT(1); }
        else                { CP_WAIT(0); }
        __syncthreads();

        #pragma unroll
        for (int ks = 0; ks < 2; ks++) {
            int chi = ks * 2 + aoff;
            uint32_t afh[2][4], afl[2][4];
            #pragma unroll
            for (int t = 0; t < 2; t++) {
                int row = wm + 16 * t + arow;
                uint32_t ra = sA[cur] + row * 128;
                LDSM_X4(afh[t], ra + ((chi       ^ (row & 7)) << 4));
                LDSM_X4(afl[t], ra + (((chi + 4) ^ (row & 7)) << 4));
            }
            int cb = ks * 2 + boff;
            uint32_t bf[4][4];
            #pragma unroll
            for (int p = 0; p < 4; p++) {
                int row = wn + 16 * p + brow;
                LDSM_X4(bf[p], sB[cur] + row * 64 + ((cb ^ ((row >> 1) & 3)) << 4));
            }
            #pragma unroll
            for (int t = 0; t < 2; t++)
                #pragma unroll
                for (int j = 0; j < 8; j++) {
                    uint32_t b0 = bf[j >> 1][2 * (j & 1)], b1 = bf[j >> 1][2 * (j & 1) + 1];
                    MMA16816(c[t][j], afh[t], b0, b1);
                    MMA16816(c[t][j], afl[t], b0, b1);
                }
        }
        __syncthreads();
    }

    // ---- epilogue: direct fragment stores (float2) ----
    int rbase = m0 + wm + (lane >> 2);
    int cbase = n0 + wn + (lane & 3) * 2;
    #pragma unroll
    for (int t = 0; t < 2; t++) {
        #pragma unroll
        for (int j = 0; j < 8; j++) {
            int col = cbase + 8 * j;
            #pragma unroll
            for (int h = 0; h < 2; h++) {
                int row = rbase + 16 * t + 8 * h;
                float v0 = c[t][j][2 * h], v1 = c[t][j][2 * h + 1];
                if (EPI == 1) {
                    float t0 = v0 + extra[col],     t1 = v1 + extra[col + 1];
                    v0 = (t0 > 20.f) ? t0 : log1pf(__expf(t0));
                    v1 = (t1 > 20.f) ? t1 : log1pf(__expf(t1));
                } else if (EPI == 2) {
                    v0 += extra[(size_t)row * lde + col];
                    v1 += extra[(size_t)row * lde + col + 1];
                }
                float2 st = make_float2(v0, v1);
                *(float2*)(C + (size_t)row * ldc + col) = st;
            }
        }
    }
}

// ---------------- zero kernel ----------------
__global__ __launch_bounds__(256) void zero_kernel(float* p, int n4) {
    int i = blockIdx.x * blockDim.x + threadIdx.x;
    if (i < n4) ((float4*)p)[i] = make_float4(0.f, 0.f, 0.f, 0.f);
}

// ---------------- x_proj: 64x64 split-K fp32 GEMM, atomic epilogue ----------------
__global__ __launch_bounds__(256) void gemm64_splitk(
    const float* __restrict__ A, int lda,
    const float* __restrict__ W, int ldb,
    float* __restrict__ C, int ldc,
    int N, int KS)
{
    const int BK = 16;
    __shared__ __align__(16) float As[BK][64];
    __shared__ __align__(16) float Bs[BK][64];

    int tid = threadIdx.x;
    int tx = tid & 15, ty = tid >> 4;
    int m0 = blockIdx.y * 64;
    int n0 = blockIdx.x * 64;
    int koff = blockIdx.z * KS;

    int a_m = tid >> 2;
    int a_k = (tid & 3) * 4;
    int b_k = tid >> 4;
    int b_n = (tid & 15) * 4;

    float acc[4][4];
    #pragma unroll
    for (int i = 0; i < 4; i++)
        #pragma unroll
        for (int j = 0; j < 4; j++) acc[i][j] = 0.f;

    for (int k0 = koff; k0 < koff + KS; k0 += BK) {
        float4 av = *(const float4*)(A + (size_t)(m0 + a_m) * lda + k0 + a_k);
        As[a_k + 0][a_m] = av.x;
        As[a_k + 1][a_m] = av.y;
        As[a_k + 2][a_m] = av.z;
        As[a_k + 3][a_m] = av.w;
        float4 bv = make_float4(0.f, 0.f, 0.f, 0.f);
        if (n0 + b_n < N)
            bv = *(const float4*)(W + (size_t)(k0 + b_k) * ldb + n0 + b_n);
        *(float4*)&Bs[b_k][b_n] = bv;
        __syncthreads();

        #pragma unroll
        for (int k = 0; k < BK; k++) {
            float4 a = *(const float4*)&As[k][ty * 4];
            float4 b = *(const float4*)&Bs[k][tx * 4];
            float ar[4] = {a.x, a.y, a.z, a.w};
            float br[4] = {b.x, b.y, b.z, b.w};
            #pragma unroll
            for (int i = 0; i < 4; i++)
                #pragma unroll
                for (int j = 0; j < 4; j++)
                    acc[i][j] = fmaf(ar[i], br[j], acc[i][j]);
        }
        __syncthreads();
    }

    #pragma unroll
    for (int i = 0; i < 4; i++) {
        int row = m0 + ty * 4 + i;
        #pragma unroll
        for (int j = 0; j < 4; j++) {
            int col = n0 + tx * 4 + j;
            if (col < N)
                atomicAdd(C + (size_t)row * ldc + col, acc[i][j]);
        }
    }
}

// ---------------- depthwise causal conv (k=4) + SiLU ----------------
__global__ __launch_bounds__(256) void conv_silu_kernel(const float* __restrict__ w,
                                                        const float* __restrict__ cb) {
    int idx = blockIdx.x * blockDim.x + threadIdx.x;
    if (idx >= M_ROWS * DIN) return;
    int d = idx & (DIN - 1);
    int row = idx >> 11;
    int l = row & (L_SZ - 1);
    float acc = cb[d];
    const float* up = g_xz + (size_t)row * (2 * DIN) + d;
    const float* wd = w + d * 4;
    #pragma unroll
    for (int j = 0; j < 4; j++) {
        int ll = l - 3 + j;
        if (ll >= 0) acc = fmaf(wd[j], up[(j - 3) * (2 * DIN)], acc);
    }
    g_uc[idx] = acc / (1.f + __expf(-acc));
}

// ---------------- selective scan: batched loads; writes fp16 [hi|lo] to gAy ----------------
__global__ __launch_bounds__(128) void scan_kernel(const float* __restrict__ A_log,
                                                   const float* __restrict__ Dp) {
    int warp = blockIdx.x * (blockDim.x >> 5) + (threadIdx.x >> 5);
    int lane = threadIdx.x & 31;
    int half = lane >> 4;
    int n = lane & 15;
    int ch = warp * 2 + half;
    int b = ch >> 11;
    int d = ch & (DIN - 1);

    float A  = -__expf(A_log[d * NST + n]);
    float Dd = Dp[d];
    float h = 0.f;

    const float* delta_p = g_delta + (size_t)b * L_SZ * DIN + d;
    const float* u_p     = g_uc    + (size_t)b * L_SZ * DIN + d;
    const float* bc_p    = g_dbc   + (size_t)b * L_SZ * XPROJ_N;
    const float* z_p     = g_xz    + (size_t)b * L_SZ * (2 * DIN) + DIN + d;
    __half*      yh_p    = gAy     + (size_t)b * L_SZ * (2 * DIN) + d;

    for (int l0 = 0; l0 < L_SZ; l0 += 8) {
        float dl[8], uu[8], Bv[8], Cv[8];
        #pragma unroll
        for (int j = 0; j < 8; j++) {
            size_t l = l0 + j;
            dl[j] = delta_p[l * DIN];
            uu[j] = u_p[l * DIN];
            Bv[j] = bc_p[l * XPROJ_N + DTR + n];
            Cv[j] = bc_p[l * XPROJ_N + DTR + NST + n];
        }
        float p[8];
        #pragma unroll
        for (int j = 0; j < 8; j++) {
            h = fmaf(__expf(dl[j] * A), h, (dl[j] * uu[j]) * Bv[j]);
            p[j] = h * Cv[j];
        }
        #pragma unroll
        for (int j = 0; j < 8; j++) {
            float q = p[j];
            q += __shfl_xor_sync(0xffffffffu, q, 8);
            q += __shfl_xor_sync(0xffffffffu, q, 4);
            q += __shfl_xor_sync(0xffffffffu, q, 2);
            q += __shfl_xor_sync(0xffffffffu, q, 1);
            if (n == 0) {
                float y = q + uu[j] * Dd;
                float z = z_p[(size_t)(l0 + j) * (2 * DIN)];
                float yg = y * (z / (1.f + __expf(-z)));
                __half hi = __float2half_rn(yg);
                __half lo = __float2half_rn(yg - __half2float(hi));
                yh_p[(size_t)(l0 + j) * (2 * DIN)]       = hi;
                yh_p[(size_t)(l0 + j) * (2 * DIN) + DIN] = lo;
            }
        }
    }
}

// ---------------- launch ----------------
extern "C" void kernel_launch(void* const* d_in, const int* in_sizes, int n_in,
                              void* d_out, int out_size) {
    const float* x         = (const float*)d_in[0];
    const float* in_proj_w = (const float*)d_in[1];
    const float* conv_w    = (const float*)d_in[2];
    const float* conv_b    = (const float*)d_in[3];
    const float* x_proj_w  = (const float*)d_in[4];
    const float* dt_proj_w = (const float*)d_in[5];
    const float* dt_proj_b = (const float*)d_in[6];
    const float* A_log     = (const float*)d_in[7];
    const float* Dp        = (const float*)d_in[8];
    const float* out_proj_w= (const float*)d_in[9];
    const float* ln_g      = (const float*)d_in[10];
    const float* ln_b      = (const float*)d_in[11];
    float* out = (float*)d_out;

    float *p_xz, *p_uc, *p_dbc, *p_delta;
    cudaGetSymbolAddress((void**)&p_xz,    g_xz);
    cudaGetSymbolAddress((void**)&p_uc,    g_uc);
    cudaGetSymbolAddress((void**)&p_dbc,   g_dbc);
    cudaGetSymbolAddress((void**)&p_delta, g_delta);
    __half *pA1, *pB1, *pAdt, *pBdt, *pAy, *pBo;
    cudaGetSymbolAddress((void**)&pA1,  gA1);
    cudaGetSymbolAddress((void**)&pB1,  gB1);
    cudaGetSymbolAddress((void**)&pAdt, gAdt);
    cudaGetSymbolAddress((void**)&pBdt, gBdt);
    cudaGetSymbolAddress((void**)&pAy,  gAy);
    cudaGetSymbolAddress((void**)&pBo,  gBo);

    // [0] in_proj weight -> fp16 hi (transposed)
    wexpT<<<dim3((2*DIN)/32, DM/32), 256>>>(in_proj_w, pB1, DM, 2*DIN);

    // [1] layernorm + fp16 [hi|lo] expand
    ln_expand<<<M_ROWS, 256>>>(x, ln_g, ln_b);

    // [2] xz = xn @ in_proj_w   (shared-B split, K = 1024)
    gemm_mma<0><<<dim3((2*DIN)/128, M_ROWS/128), 256>>>(
        pA1, pB1, DM, p_xz, 2*DIN, nullptr, 0);

    // [3] uc = silu(conv(u))
    conv_silu_kernel<<<(M_ROWS * DIN + 255) / 256, 256>>>(conv_w, conv_b);

    // [4] zero x_proj accumulator
    zero_kernel<<<(M_ROWS * XPROJ_N / 4 + 255) / 256, 256>>>(p_dbc, M_ROWS * XPROJ_N / 4);

    // [5] dbc += uc @ x_proj_w (fp32 split-K)
    {
        dim3 grid((XPROJ_N + 63) / 64, M_ROWS / 64, 8);
        gemm64_splitk<<<grid, 256>>>(p_uc, DIN, x_proj_w, XPROJ_N,
                                     p_dbc, XPROJ_N, XPROJ_N, DIN / 8);
    }

    // [6][7] dt weight + dt slice expand
    wexpT<<<dim3(DIN/32, DTR/32), 256>>>(dt_proj_w, pBdt, DTR, DIN);
    aexp<<<(M_ROWS * (DTR/4) + 255) / 256, 256>>>(p_dbc, XPROJ_N, pAdt, DTR, M_ROWS);

    // [8] delta = softplus(dt @ dt_proj_w + b)   (K = 64)
    gemm_mma<1><<<dim3(DIN/128, M_ROWS/128), 256>>>(
        pAdt, pBdt, DTR, p_delta, DIN, dt_proj_b, 0);

    // [9] out_proj weight
    wexpT<<<dim3(DM/32, DIN/32), 256>>>(out_proj_w, pBo, DIN, DM);

    // [10] selective scan + gate -> writes gAy directly as [hi|lo]
    scan_kernel<<<(B_SZ * DIN / 2) / 4, 128>>>(A_log, Dp);

    // [11] out = yz @ out_proj_w + x   (K = 2048)
    gemm_mma<2><<<dim3(DM/128, M_ROWS/128), 256>>>(
        pAy, pBo, DIN, out, DM, x, DM);
}